// round 16
// baseline (speedup 1.0000x reference)
#include <cuda_runtime.h>
#include <cuda_fp16.h>
#include <cstdint>

// SparseProjection: out[b,k] = dot(weight[indices[b,k]], inp[b]) + bias[indices[b,k]]
// B=4096, K=128, D=512, V=128000.
// CHAMPION pipeline (70.7us @ CAP=16, restored); single change this round:
// prep_fused grid 1024 -> 2048 (one float4 per thread; TLP doubles in the
// latency-bound convert).
//   1) prep_fused: probe idx dtype + zero counts + fp32->fp16 convert of inp
//   2) scatter_bucket: bucket entries by vocab index (1 entry/thread)
//   3) csr_main: one warp per vocab row; weight -> half2 regs once (streaming
//      loads), HFMA2 dots vs fp16 inp (L2-resident), 4-entry ILP uint4
//      gathers, int4 bucket loads, overflow tail blocks.

#define D_DIM 512
#define D4 (D_DIM / 4)
#define B_FIXED 4096
#define V_FIXED 128000
#define BK_FIXED (B_FIXED * 128)
#define CAP 16            // bucket capacity; 64B rows (sector-aligned); P(>16)~3e-6
#define OVF_CAP 65536
#define OVF_BLOCKS 16

// ---- static device scratch (no allocation allowed) ----
__device__ int    g_idx_is64;
__device__ int    g_counts[V_FIXED];
__device__ int    g_bucket[(size_t)V_FIXED * CAP];   // 8 MB, rows 64B-aligned
__device__ int    g_overflow[OVF_CAP];
__device__ int    g_overflow_n;
__device__ __half g_inp_h[B_FIXED * D_DIM];          // 4 MB fp16 copy of inp

__device__ __forceinline__ long long load_index(const void* idx, size_t i,
                                                int is64, long long vocab)
{
    long long v = is64 ? ((const long long*)idx)[i]
                       : (long long)((const int*)idx)[i];
    v = v < 0 ? 0 : v;
    v = v >= vocab ? vocab - 1 : v;
    return v;
}

// ------ fused prep: dtype probe + zero counts + fp32->fp16 convert ---------
__global__ void prep_fused(const float4* __restrict__ inp, int n4, int V,
                           const long long* __restrict__ idx64,
                           long long n_elems, long long vocab)
{
    int i = blockIdx.x * blockDim.x + threadIdx.x;
    int stride = gridDim.x * blockDim.x;

    if (blockIdx.x == 0 && threadIdx.x < 32) {
        // dtype probe: int32 data viewed as int64 has garbage high words.
        const int lane = threadIdx.x;
        int ok = 1;
        long long n = n_elems < 256 ? n_elems : 256;
        for (long long j = lane; j < n; j += 32) {
            long long v = idx64[j];
            if (v < 0 || v >= vocab) ok = 0;
        }
        ok = __all_sync(0xFFFFFFFFu, ok);
        if (lane == 0) { g_idx_is64 = ok; g_overflow_n = 0; }
    }

    for (int j = i; j < V; j += stride) g_counts[j] = 0;

    // 2-wide ILP when threads cover less than n4; with grid 2048x256 each
    // thread handles exactly one float4 via the tail path.
    int j = i;
    for (; j + stride < n4; j += 2 * stride) {
        float4 f0 = inp[j];
        float4 f1 = inp[j + stride];
        __half2 l0 = __floats2half2_rn(f0.x, f0.y);
        __half2 h0 = __floats2half2_rn(f0.z, f0.w);
        __half2 l1 = __floats2half2_rn(f1.x, f1.y);
        __half2 h1 = __floats2half2_rn(f1.z, f1.w);
        uint2 p0, p1;
        p0.x = *(const unsigned int*)&l0;
        p0.y = *(const unsigned int*)&h0;
        p1.x = *(const unsigned int*)&l1;
        p1.y = *(const unsigned int*)&h1;
        ((uint2*)g_inp_h)[j] = p0;
        ((uint2*)g_inp_h)[j + stride] = p1;
    }
    if (j < n4) {
        float4 f = inp[j];
        __half2 lo = __floats2half2_rn(f.x, f.y);
        __half2 hi = __floats2half2_rn(f.z, f.w);
        uint2 p;
        p.x = *(const unsigned int*)&lo;
        p.y = *(const unsigned int*)&hi;
        ((uint2*)g_inp_h)[j] = p;
    }
}

// ---------------- bucket scatter (no histogram / scan needed) --------------
__global__ void scatter_bucket(const void* __restrict__ idx, int BK, long long vocab)
{
    int e = blockIdx.x * blockDim.x + threadIdx.x;
    if (e < BK) {
        int v = (int)load_index(idx, (size_t)e, g_idx_is64, vocab);
        int pos = atomicAdd(&g_counts[v], 1);
        if (pos < CAP) {
            g_bucket[(size_t)v * CAP + pos] = e;
        } else {
            int o = atomicAdd(&g_overflow_n, 1);
            if (o < OVF_CAP) g_overflow[o] = e;
        }
    }
}

// ---------------- helpers ----------------
__device__ __forceinline__ float dot_w_h(float4 w, uint2 p)
{
    float2 lo = __half22float2(*(const __half2*)&p.x);
    float2 hi = __half22float2(*(const __half2*)&p.y);
    return w.x * lo.x + w.y * lo.y + w.z * hi.x + w.w * hi.y;
}

// Dot of 16 halves (two uint4 = two 8-half groups) against 8 half2 weights.
__device__ __forceinline__ float dot16_h2(const __half2* w, uint4 q0, uint4 q1)
{
    const __half2* h0 = (const __half2*)&q0;
    const __half2* h1 = (const __half2*)&q1;
    __half2 s0 = __hmul2(w[0], h0[0]);
    s0 = __hfma2(w[1], h0[1], s0);
    s0 = __hfma2(w[2], h0[2], s0);
    s0 = __hfma2(w[3], h0[3], s0);
    __half2 s1 = __hmul2(w[4], h1[0]);
    s1 = __hfma2(w[5], h1[1], s1);
    s1 = __hfma2(w[6], h1[2], s1);
    s1 = __hfma2(w[7], h1[3], s1);
    float2 f = __half22float2(__hadd2(s0, s1));
    return f.x + f.y;
}

// ---------------- main kernel: one warp per vocab row + overflow tail ------
__global__ __launch_bounds__(128)
void csr_main(const float4* __restrict__ weight,
              const float*  __restrict__ bias,
              float* __restrict__ out,
              int V, int K, int kshift, int rowBlocks,
              const void* __restrict__ idx, long long vocab)
{
    const int warp = threadIdx.x >> 5;
    const int lane = threadIdx.x & 31;

    if (blockIdx.x >= rowBlocks) {
        // ---- overflow fixup (expected ~empty at CAP=16) ----
        int n = g_overflow_n;
        if (n > OVF_CAP) n = OVF_CAP;
        if (n == 0) return;
        const int is64 = g_idx_is64;
        const int wpb = blockDim.x >> 5;
        for (int i = (blockIdx.x - rowBlocks) * wpb + warp;
             i < n; i += OVF_BLOCKS * wpb) {
            int e = g_overflow[i];
            int b = e / K;
            long long v = load_index(idx, (size_t)e, is64, vocab);
            const float4* wr = weight + v * D4;
            const uint2* r0 = (const uint2*)(g_inp_h + (size_t)b * D_DIM);
            float acc = dot_w_h(wr[lane +  0], r0[lane +  0])
                      + dot_w_h(wr[lane + 32], r0[lane + 32])
                      + dot_w_h(wr[lane + 64], r0[lane + 64])
                      + dot_w_h(wr[lane + 96], r0[lane + 96]);
            #pragma unroll
            for (int off = 16; off > 0; off >>= 1)
                acc += __shfl_xor_sync(0xFFFFFFFFu, acc, off);
            if (lane == 0) out[e] = acc + __ldg(bias + v);
        }
        return;
    }

    const int v = blockIdx.x * 4 + warp;
    if (v >= V) return;

    int cnt = g_counts[v];
    if (cnt <= 0) return;
    if (cnt > CAP) cnt = CAP;      // excess handled by overflow tail

    // Load weight row (sequential stream, evict-first) and convert once to
    // half2 regs. Lane L owns halves [8L, 8L+8) and [256+8L, 256+8L+8),
    // matching the uint4 inp-load layout below.
    const float4* wr = weight + (size_t)v * D4;
    float4 wa = __ldcs(wr + 2 * lane);
    float4 wb = __ldcs(wr + 2 * lane + 1);
    float4 wc = __ldcs(wr + 64 + 2 * lane);
    float4 wd = __ldcs(wr + 64 + 2 * lane + 1);
    __half2 wh[8];
    wh[0] = __floats2half2_rn(wa.x, wa.y);
    wh[1] = __floats2half2_rn(wa.z, wa.w);
    wh[2] = __floats2half2_rn(wb.x, wb.y);
    wh[3] = __floats2half2_rn(wb.z, wb.w);
    wh[4] = __floats2half2_rn(wc.x, wc.y);
    wh[5] = __floats2half2_rn(wc.z, wc.w);
    wh[6] = __floats2half2_rn(wd.x, wd.y);
    wh[7] = __floats2half2_rn(wd.z, wd.w);
    const float bv = __ldg(bias + v);
    const int* bkt = g_bucket + (size_t)v * CAP;

    int i = 0;
    // ---- 4-entry chunks: one int4 bucket load + 8 gather LDG.128 in flight
    for (; i + 4 <= cnt; i += 4) {
        int4 ee = *(const int4*)(bkt + i);           // 16B-aligned (64B rows)
        int e0 = ee.x, e1 = ee.y, e2 = ee.z, e3 = ee.w;
        int b0 = (kshift >= 0) ? (e0 >> kshift) : (e0 / K);
        int b1 = (kshift >= 0) ? (e1 >> kshift) : (e1 / K);
        int b2 = (kshift >= 0) ? (e2 >> kshift) : (e2 / K);
        int b3 = (kshift >= 0) ? (e3 >> kshift) : (e3 / K);
        const uint4* r0 = (const uint4*)(g_inp_h + (size_t)b0 * D_DIM);
        const uint4* r1 = (const uint4*)(g_inp_h + (size_t)b1 * D_DIM);
        const uint4* r2 = (const uint4*)(g_inp_h + (size_t)b2 * D_DIM);
        const uint4* r3 = (const uint4*)(g_inp_h + (size_t)b3 * D_DIM);
        uint4 q00 = r0[lane];
        uint4 q01 = r0[lane + 32];
        uint4 q10 = r1[lane];
        uint4 q11 = r1[lane + 32];
        uint4 q20 = r2[lane];
        uint4 q21 = r2[lane + 32];
        uint4 q30 = r3[lane];
        uint4 q31 = r3[lane + 32];

        float acc0 = dot16_h2(wh, q00, q01);
        float acc1 = dot16_h2(wh, q10, q11);
        float acc2 = dot16_h2(wh, q20, q21);
        float acc3 = dot16_h2(wh, q30, q31);

        #pragma unroll
        for (int off = 16; off > 0; off >>= 1) {
            acc0 += __shfl_xor_sync(0xFFFFFFFFu, acc0, off);
            acc1 += __shfl_xor_sync(0xFFFFFFFFu, acc1, off);
            acc2 += __shfl_xor_sync(0xFFFFFFFFu, acc2, off);
            acc3 += __shfl_xor_sync(0xFFFFFFFFu, acc3, off);
        }
        if (lane == 0) {
            out[e0] = acc0 + bv;
            out[e1] = acc1 + bv;
            out[e2] = acc2 + bv;
            out[e3] = acc3 + bv;
        }
    }
    // ---- 2-entry chunk ----
    if (i + 2 <= cnt) {
        int2 ee = *(const int2*)(bkt + i);           // 8B-aligned
        int e0 = ee.x, e1 = ee.y;
        int b0 = (kshift >= 0) ? (e0 >> kshift) : (e0 / K);
        int b1 = (kshift >= 0) ? (e1 >> kshift) : (e1 / K);
        const uint4* r0 = (const uint4*)(g_inp_h + (size_t)b0 * D_DIM);
        const uint4* r1 = (const uint4*)(g_inp_h + (size_t)b1 * D_DIM);
        uint4 q00 = r0[lane];
        uint4 q01 = r0[lane + 32];
        uint4 q10 = r1[lane];
        uint4 q11 = r1[lane + 32];
        float acc0 = dot16_h2(wh, q00, q01);
        float acc1 = dot16_h2(wh, q10, q11);
        #pragma unroll
        for (int off = 16; off > 0; off >>= 1) {
            acc0 += __shfl_xor_sync(0xFFFFFFFFu, acc0, off);
            acc1 += __shfl_xor_sync(0xFFFFFFFFu, acc1, off);
        }
        if (lane == 0) {
            out[e0] = acc0 + bv;
            out[e1] = acc1 + bv;
        }
        i += 2;
    }
    // ---- single entry ----
    if (i < cnt) {
        int e0 = bkt[i];
        int b0 = (kshift >= 0) ? (e0 >> kshift) : (e0 / K);
        const uint4* r0 = (const uint4*)(g_inp_h + (size_t)b0 * D_DIM);
        uint4 q00 = r0[lane];
        uint4 q01 = r0[lane + 32];
        float acc0 = dot16_h2(wh, q00, q01);
        #pragma unroll
        for (int off = 16; off > 0; off >>= 1)
            acc0 += __shfl_xor_sync(0xFFFFFFFFu, acc0, off);
        if (lane == 0) out[e0] = acc0 + bv;
    }
}

// ---------------- fallback: direct gather (proven round 2) -----------------
#define THREADS 256
#define WARPS (THREADS / 32)

__global__ __launch_bounds__(THREADS)
void sparse_proj_fallback(const float4* __restrict__ inp,
                          const void* __restrict__ indices,
                          const float4* __restrict__ weight,
                          const float* __restrict__ bias,
                          float* __restrict__ out,
                          long long vocab, int K)
{
    __shared__ float4 s_in[D4];
    const int b = blockIdx.x;
    const int tid = threadIdx.x;
    const int warp = tid >> 5;
    const int lane = tid & 31;
    const int is64 = g_idx_is64;
    const int k_per_warp = K / WARPS;

    if (tid < D4) s_in[tid] = inp[(size_t)b * D4 + tid];
    __syncthreads();

    float4 iv0 = s_in[lane +  0];
    float4 iv1 = s_in[lane + 32];
    float4 iv2 = s_in[lane + 64];
    float4 iv3 = s_in[lane + 96];

    const size_t idx_base = (size_t)b * K + (size_t)warp * k_per_warp;
    float* out_row = out + idx_base;

    for (int kk = 0; kk < k_per_warp; kk++) {
        long long r0 = load_index(indices, idx_base + kk, is64, vocab);
        const float4* w0 = weight + r0 * D4;
        float4 a0 = w0[lane +  0];
        float4 a1 = w0[lane + 32];
        float4 a2 = w0[lane + 64];
        float4 a3 = w0[lane + 96];
        float acc0 = a0.x * iv0.x + a0.y * iv0.y + a0.z * iv0.z + a0.w * iv0.w
                   + a1.x * iv1.x + a1.y * iv1.y + a1.z * iv1.z + a1.w * iv1.w
                   + a2.x * iv2.x + a2.y * iv2.y + a2.z * iv2.z + a2.w * iv2.w
                   + a3.x * iv3.x + a3.y * iv3.y + a3.z * iv3.z + a3.w * iv3.w;
        #pragma unroll
        for (int off = 16; off > 0; off >>= 1)
            acc0 += __shfl_xor_sync(0xFFFFFFFFu, acc0, off);
        if (lane == 0) out_row[kk] = acc0 + __ldg(bias + r0);
    }
}

extern "C" void kernel_launch(void* const* d_in, const int* in_sizes, int n_in,
                              void* d_out, int out_size)
{
    const float4* inp     = (const float4*)d_in[0];
    const void*   indices = d_in[1];
    const float4* weight  = (const float4*)d_in[3];
    const float*  bias    = (const float*)d_in[4];
    float*        out     = (float*)d_out;

    const long long V  = (long long)in_sizes[4];
    const int       D  = (int)((long long)in_sizes[3] / V);
    const int       B  = in_sizes[0] / D;
    const int       K  = in_sizes[1] / B;
    const int       BK = in_sizes[1];

    const bool csr_ok = (D == D_DIM) && (V <= V_FIXED) && (BK <= BK_FIXED) &&
                        ((long long)B * D <= (long long)B_FIXED * D_DIM);

    if (csr_ok) {
        const int Vi = (int)V;
        const int n4 = B * D / 4;
        const int rowBlocks = (Vi + 3) / 4;

        int kshift = -1;
        if ((K & (K - 1)) == 0) {
            kshift = 0;
            while ((1 << kshift) < K) kshift++;
        }

        prep_fused<<<2048, 256>>>(inp, n4, Vi,
                                  (const long long*)indices, BK, V);
        scatter_bucket<<<(BK + 255) / 256, 256>>>(indices, BK, V);
        csr_main<<<rowBlocks + OVF_BLOCKS, 128>>>(weight, bias, out,
                                                  Vi, K, kshift, rowBlocks,
                                                  indices, V);
    } else {
        prep_fused<<<1, 32>>>(inp, 0, 0, (const long long*)indices, BK, V);
        sparse_proj_fallback<<<B, THREADS>>>(inp, indices, weight, bias, out, V, K);
    }
}

// round 17
// speedup vs baseline: 1.0274x; 1.0274x over previous
#include <cuda_runtime.h>
#include <cuda_fp16.h>
#include <cstdint>

// SparseProjection: out[b,k] = dot(weight[indices[b,k]], inp[b]) + bias[indices[b,k]]
// B=4096, K=128, D=512, V=128000.
// CHAMPION configuration (70.7us, R14) restored exactly:
//   1) prep_fused <<<1024,256>>>: probe idx dtype + zero counts + fp32->fp16
//      convert of inp (2-wide ILP)
//   2) scatter_bucket <<<BK/256,256>>>: bucket entries by vocab index
//   3) csr_main <<<V/4+16,128>>>: one warp per vocab row; weight -> half2
//      regs once (streaming loads), HFMA2 dots vs fp16 inp (L2-resident),
//      4-entry ILP uint4 gathers, int4 bucket loads, overflow tail blocks.
// CAP=16: 64B sector-aligned bucket rows, 8MB bucket array (L2-resident with
// the 4MB fp16 inp copy); P(count>16)~3e-6 with exact overflow handling.

#define D_DIM 512
#define D4 (D_DIM / 4)
#define B_FIXED 4096
#define V_FIXED 128000
#define BK_FIXED (B_FIXED * 128)
#define CAP 16            // bucket capacity; 64B rows (sector-aligned); P(>16)~3e-6
#define OVF_CAP 65536
#define OVF_BLOCKS 16

// ---- static device scratch (no allocation allowed) ----
__device__ int    g_idx_is64;
__device__ int    g_counts[V_FIXED];
__device__ int    g_bucket[(size_t)V_FIXED * CAP];   // 8 MB, rows 64B-aligned
__device__ int    g_overflow[OVF_CAP];
__device__ int    g_overflow_n;
__device__ __half g_inp_h[B_FIXED * D_DIM];          // 4 MB fp16 copy of inp

__device__ __forceinline__ long long load_index(const void* idx, size_t i,
                                                int is64, long long vocab)
{
    long long v = is64 ? ((const long long*)idx)[i]
                       : (long long)((const int*)idx)[i];
    v = v < 0 ? 0 : v;
    v = v >= vocab ? vocab - 1 : v;
    return v;
}

// ------ fused prep: dtype probe + zero counts + fp32->fp16 convert ---------
__global__ void prep_fused(const float4* __restrict__ inp, int n4, int V,
                           const long long* __restrict__ idx64,
                           long long n_elems, long long vocab)
{
    int i = blockIdx.x * blockDim.x + threadIdx.x;
    int stride = gridDim.x * blockDim.x;

    if (blockIdx.x == 0 && threadIdx.x < 32) {
        // dtype probe: int32 data viewed as int64 has garbage high words.
        const int lane = threadIdx.x;
        int ok = 1;
        long long n = n_elems < 256 ? n_elems : 256;
        for (long long j = lane; j < n; j += 32) {
            long long v = idx64[j];
            if (v < 0 || v >= vocab) ok = 0;
        }
        ok = __all_sync(0xFFFFFFFFu, ok);
        if (lane == 0) { g_idx_is64 = ok; g_overflow_n = 0; }
    }

    for (int j = i; j < V; j += stride) g_counts[j] = 0;

    // 2-wide ILP: two independent LDG.128 in flight per iteration.
    int j = i;
    for (; j + stride < n4; j += 2 * stride) {
        float4 f0 = inp[j];
        float4 f1 = inp[j + stride];
        __half2 l0 = __floats2half2_rn(f0.x, f0.y);
        __half2 h0 = __floats2half2_rn(f0.z, f0.w);
        __half2 l1 = __floats2half2_rn(f1.x, f1.y);
        __half2 h1 = __floats2half2_rn(f1.z, f1.w);
        uint2 p0, p1;
        p0.x = *(const unsigned int*)&l0;
        p0.y = *(const unsigned int*)&h0;
        p1.x = *(const unsigned int*)&l1;
        p1.y = *(const unsigned int*)&h1;
        ((uint2*)g_inp_h)[j] = p0;
        ((uint2*)g_inp_h)[j + stride] = p1;
    }
    if (j < n4) {
        float4 f = inp[j];
        __half2 lo = __floats2half2_rn(f.x, f.y);
        __half2 hi = __floats2half2_rn(f.z, f.w);
        uint2 p;
        p.x = *(const unsigned int*)&lo;
        p.y = *(const unsigned int*)&hi;
        ((uint2*)g_inp_h)[j] = p;
    }
}

// ---------------- bucket scatter (no histogram / scan needed) --------------
__global__ void scatter_bucket(const void* __restrict__ idx, int BK, long long vocab)
{
    int e = blockIdx.x * blockDim.x + threadIdx.x;
    if (e < BK) {
        int v = (int)load_index(idx, (size_t)e, g_idx_is64, vocab);
        int pos = atomicAdd(&g_counts[v], 1);
        if (pos < CAP) {
            g_bucket[(size_t)v * CAP + pos] = e;
        } else {
            int o = atomicAdd(&g_overflow_n, 1);
            if (o < OVF_CAP) g_overflow[o] = e;
        }
    }
}

// ---------------- helpers ----------------
__device__ __forceinline__ float dot_w_h(float4 w, uint2 p)
{
    float2 lo = __half22float2(*(const __half2*)&p.x);
    float2 hi = __half22float2(*(const __half2*)&p.y);
    return w.x * lo.x + w.y * lo.y + w.z * hi.x + w.w * hi.y;
}

// Dot of 16 halves (two uint4 = two 8-half groups) against 8 half2 weights.
__device__ __forceinline__ float dot16_h2(const __half2* w, uint4 q0, uint4 q1)
{
    const __half2* h0 = (const __half2*)&q0;
    const __half2* h1 = (const __half2*)&q1;
    __half2 s0 = __hmul2(w[0], h0[0]);
    s0 = __hfma2(w[1], h0[1], s0);
    s0 = __hfma2(w[2], h0[2], s0);
    s0 = __hfma2(w[3], h0[3], s0);
    __half2 s1 = __hmul2(w[4], h1[0]);
    s1 = __hfma2(w[5], h1[1], s1);
    s1 = __hfma2(w[6], h1[2], s1);
    s1 = __hfma2(w[7], h1[3], s1);
    float2 f = __half22float2(__hadd2(s0, s1));
    return f.x + f.y;
}

// ---------------- main kernel: one warp per vocab row + overflow tail ------
__global__ __launch_bounds__(128)
void csr_main(const float4* __restrict__ weight,
              const float*  __restrict__ bias,
              float* __restrict__ out,
              int V, int K, int kshift, int rowBlocks,
              const void* __restrict__ idx, long long vocab)
{
    const int warp = threadIdx.x >> 5;
    const int lane = threadIdx.x & 31;

    if (blockIdx.x >= rowBlocks) {
        // ---- overflow fixup (expected ~empty at CAP=16) ----
        int n = g_overflow_n;
        if (n > OVF_CAP) n = OVF_CAP;
        if (n == 0) return;
        const int is64 = g_idx_is64;
        const int wpb = blockDim.x >> 5;
        for (int i = (blockIdx.x - rowBlocks) * wpb + warp;
             i < n; i += OVF_BLOCKS * wpb) {
            int e = g_overflow[i];
            int b = e / K;
            long long v = load_index(idx, (size_t)e, is64, vocab);
            const float4* wr = weight + v * D4;
            const uint2* r0 = (const uint2*)(g_inp_h + (size_t)b * D_DIM);
            float acc = dot_w_h(wr[lane +  0], r0[lane +  0])
                      + dot_w_h(wr[lane + 32], r0[lane + 32])
                      + dot_w_h(wr[lane + 64], r0[lane + 64])
                      + dot_w_h(wr[lane + 96], r0[lane + 96]);
            #pragma unroll
            for (int off = 16; off > 0; off >>= 1)
                acc += __shfl_xor_sync(0xFFFFFFFFu, acc, off);
            if (lane == 0) out[e] = acc + __ldg(bias + v);
        }
        return;
    }

    const int v = blockIdx.x * 4 + warp;
    if (v >= V) return;

    int cnt = g_counts[v];
    if (cnt <= 0) return;
    if (cnt > CAP) cnt = CAP;      // excess handled by overflow tail

    // Load weight row (sequential stream, evict-first) and convert once to
    // half2 regs. Lane L owns halves [8L, 8L+8) and [256+8L, 256+8L+8),
    // matching the uint4 inp-load layout below.
    const float4* wr = weight + (size_t)v * D4;
    float4 wa = __ldcs(wr + 2 * lane);
    float4 wb = __ldcs(wr + 2 * lane + 1);
    float4 wc = __ldcs(wr + 64 + 2 * lane);
    float4 wd = __ldcs(wr + 64 + 2 * lane + 1);
    __half2 wh[8];
    wh[0] = __floats2half2_rn(wa.x, wa.y);
    wh[1] = __floats2half2_rn(wa.z, wa.w);
    wh[2] = __floats2half2_rn(wb.x, wb.y);
    wh[3] = __floats2half2_rn(wb.z, wb.w);
    wh[4] = __floats2half2_rn(wc.x, wc.y);
    wh[5] = __floats2half2_rn(wc.z, wc.w);
    wh[6] = __floats2half2_rn(wd.x, wd.y);
    wh[7] = __floats2half2_rn(wd.z, wd.w);
    const float bv = __ldg(bias + v);
    const int* bkt = g_bucket + (size_t)v * CAP;

    int i = 0;
    // ---- 4-entry chunks: one int4 bucket load + 8 gather LDG.128 in flight
    for (; i + 4 <= cnt; i += 4) {
        int4 ee = *(const int4*)(bkt + i);           // 16B-aligned (64B rows)
        int e0 = ee.x, e1 = ee.y, e2 = ee.z, e3 = ee.w;
        int b0 = (kshift >= 0) ? (e0 >> kshift) : (e0 / K);
        int b1 = (kshift >= 0) ? (e1 >> kshift) : (e1 / K);
        int b2 = (kshift >= 0) ? (e2 >> kshift) : (e2 / K);
        int b3 = (kshift >= 0) ? (e3 >> kshift) : (e3 / K);
        const uint4* r0 = (const uint4*)(g_inp_h + (size_t)b0 * D_DIM);
        const uint4* r1 = (const uint4*)(g_inp_h + (size_t)b1 * D_DIM);
        const uint4* r2 = (const uint4*)(g_inp_h + (size_t)b2 * D_DIM);
        const uint4* r3 = (const uint4*)(g_inp_h + (size_t)b3 * D_DIM);
        uint4 q00 = r0[lane];
        uint4 q01 = r0[lane + 32];
        uint4 q10 = r1[lane];
        uint4 q11 = r1[lane + 32];
        uint4 q20 = r2[lane];
        uint4 q21 = r2[lane + 32];
        uint4 q30 = r3[lane];
        uint4 q31 = r3[lane + 32];

        float acc0 = dot16_h2(wh, q00, q01);
        float acc1 = dot16_h2(wh, q10, q11);
        float acc2 = dot16_h2(wh, q20, q21);
        float acc3 = dot16_h2(wh, q30, q31);

        #pragma unroll
        for (int off = 16; off > 0; off >>= 1) {
            acc0 += __shfl_xor_sync(0xFFFFFFFFu, acc0, off);
            acc1 += __shfl_xor_sync(0xFFFFFFFFu, acc1, off);
            acc2 += __shfl_xor_sync(0xFFFFFFFFu, acc2, off);
            acc3 += __shfl_xor_sync(0xFFFFFFFFu, acc3, off);
        }
        if (lane == 0) {
            out[e0] = acc0 + bv;
            out[e1] = acc1 + bv;
            out[e2] = acc2 + bv;
            out[e3] = acc3 + bv;
        }
    }
    // ---- 2-entry chunk ----
    if (i + 2 <= cnt) {
        int2 ee = *(const int2*)(bkt + i);           // 8B-aligned
        int e0 = ee.x, e1 = ee.y;
        int b0 = (kshift >= 0) ? (e0 >> kshift) : (e0 / K);
        int b1 = (kshift >= 0) ? (e1 >> kshift) : (e1 / K);
        const uint4* r0 = (const uint4*)(g_inp_h + (size_t)b0 * D_DIM);
        const uint4* r1 = (const uint4*)(g_inp_h + (size_t)b1 * D_DIM);
        uint4 q00 = r0[lane];
        uint4 q01 = r0[lane + 32];
        uint4 q10 = r1[lane];
        uint4 q11 = r1[lane + 32];
        float acc0 = dot16_h2(wh, q00, q01);
        float acc1 = dot16_h2(wh, q10, q11);
        #pragma unroll
        for (int off = 16; off > 0; off >>= 1) {
            acc0 += __shfl_xor_sync(0xFFFFFFFFu, acc0, off);
            acc1 += __shfl_xor_sync(0xFFFFFFFFu, acc1, off);
        }
        if (lane == 0) {
            out[e0] = acc0 + bv;
            out[e1] = acc1 + bv;
        }
        i += 2;
    }
    // ---- single entry ----
    if (i < cnt) {
        int e0 = bkt[i];
        int b0 = (kshift >= 0) ? (e0 >> kshift) : (e0 / K);
        const uint4* r0 = (const uint4*)(g_inp_h + (size_t)b0 * D_DIM);
        uint4 q00 = r0[lane];
        uint4 q01 = r0[lane + 32];
        float acc0 = dot16_h2(wh, q00, q01);
        #pragma unroll
        for (int off = 16; off > 0; off >>= 1)
            acc0 += __shfl_xor_sync(0xFFFFFFFFu, acc0, off);
        if (lane == 0) out[e0] = acc0 + bv;
    }
}

// ---------------- fallback: direct gather (proven round 2) -----------------
#define THREADS 256
#define WARPS (THREADS / 32)

__global__ __launch_bounds__(THREADS)
void sparse_proj_fallback(const float4* __restrict__ inp,
                          const void* __restrict__ indices,
                          const float4* __restrict__ weight,
                          const float* __restrict__ bias,
                          float* __restrict__ out,
                          long long vocab, int K)
{
    __shared__ float4 s_in[D4];
    const int b = blockIdx.x;
    const int tid = threadIdx.x;
    const int warp = tid >> 5;
    const int lane = tid & 31;
    const int is64 = g_idx_is64;
    const int k_per_warp = K / WARPS;

    if (tid < D4) s_in[tid] = inp[(size_t)b * D4 + tid];
    __syncthreads();

    float4 iv0 = s_in[lane +  0];
    float4 iv1 = s_in[lane + 32];
    float4 iv2 = s_in[lane + 64];
    float4 iv3 = s_in[lane + 96];

    const size_t idx_base = (size_t)b * K + (size_t)warp * k_per_warp;
    float* out_row = out + idx_base;

    for (int kk = 0; kk < k_per_warp; kk++) {
        long long r0 = load_index(indices, idx_base + kk, is64, vocab);
        const float4* w0 = weight + r0 * D4;
        float4 a0 = w0[lane +  0];
        float4 a1 = w0[lane + 32];
        float4 a2 = w0[lane + 64];
        float4 a3 = w0[lane + 96];
        float acc0 = a0.x * iv0.x + a0.y * iv0.y + a0.z * iv0.z + a0.w * iv0.w
                   + a1.x * iv1.x + a1.y * iv1.y + a1.z * iv1.z + a1.w * iv1.w
                   + a2.x * iv2.x + a2.y * iv2.y + a2.z * iv2.z + a2.w * iv2.w
                   + a3.x * iv3.x + a3.y * iv3.y + a3.z * iv3.z + a3.w * iv3.w;
        #pragma unroll
        for (int off = 16; off > 0; off >>= 1)
            acc0 += __shfl_xor_sync(0xFFFFFFFFu, acc0, off);
        if (lane == 0) out_row[kk] = acc0 + __ldg(bias + r0);
    }
}

extern "C" void kernel_launch(void* const* d_in, const int* in_sizes, int n_in,
                              void* d_out, int out_size)
{
    const float4* inp     = (const float4*)d_in[0];
    const void*   indices = d_in[1];
    const float4* weight  = (const float4*)d_in[3];
    const float*  bias    = (const float*)d_in[4];
    float*        out     = (float*)d_out;

    const long long V  = (long long)in_sizes[4];
    const int       D  = (int)((long long)in_sizes[3] / V);
    const int       B  = in_sizes[0] / D;
    const int       K  = in_sizes[1] / B;
    const int       BK = in_sizes[1];

    const bool csr_ok = (D == D_DIM) && (V <= V_FIXED) && (BK <= BK_FIXED) &&
                        ((long long)B * D <= (long long)B_FIXED * D_DIM);

    if (csr_ok) {
        const int Vi = (int)V;
        const int n4 = B * D / 4;
        const int rowBlocks = (Vi + 3) / 4;

        int kshift = -1;
        if ((K & (K - 1)) == 0) {
            kshift = 0;
            while ((1 << kshift) < K) kshift++;
        }

        prep_fused<<<1024, 256>>>(inp, n4, Vi,
                                  (const long long*)indices, BK, V);
        scatter_bucket<<<(BK + 255) / 256, 256>>>(indices, BK, V);
        csr_main<<<rowBlocks + OVF_BLOCKS, 128>>>(weight, bias, out,
                                                  Vi, K, kshift, rowBlocks,
                                                  indices, V);
    } else {
        prep_fused<<<1, 32>>>(inp, 0, 0, (const long long*)indices, BK, V);
        sparse_proj_fallback<<<B, THREADS>>>(inp, indices, weight, bias, out, V, K);
    }
}